// round 2
// baseline (speedup 1.0000x reference)
#include <cuda_runtime.h>
#include <math.h>
#include <stdint.h>

// Problem constants
#define BB 4
#define KK 2048
#define NN 4096
#define CIN 61
#define CH 64          // IN channels
#define H1C 128
#define OUTC 64
#define HEADS 4
#define KNBR 32
#define NBK (BB*KK)            // 8192 queries
#define CNTF 262144.0          // NBK*KNBR

// Scratch (static device globals — allocation-free)
__device__ float g_comb[(size_t)NBK * KNBR * CH];  // 64 MB
__device__ float g_part[(size_t)NBK * 128];        // per-block BN partials (sum[64], sumsq[64])
__device__ float g_stats[128];                     // mean[64], rstd*gamma[64]
__device__ float g_A[516];                         // folded att: A[128][4] + c0[4]

// ---------------------------------------------------------------------------
// Kernel 1: fold attention weights:  A[c][h] = sum_o att_w[c, h*64+o]*att_q[h,o]
// ---------------------------------------------------------------------------
__global__ void k_prep(const float* __restrict__ att_w,
                       const float* __restrict__ att_b,
                       const float* __restrict__ att_q) {
    int t = blockIdx.x * blockDim.x + threadIdx.x;
    if (t < 512) {
        int c = t >> 2, h = t & 3;
        float s = 0.f;
        #pragma unroll 8
        for (int o = 0; o < 64; o++)
            s += att_w[c * 256 + h * 64 + o] * att_q[h * 64 + o];
        g_A[t] = s;
    }
    if (t < 4) {
        float s = 0.f;
        #pragma unroll 8
        for (int o = 0; o < 64; o++)
            s += att_b[t * 64 + o] * att_q[t * 64 + o];
        g_A[512 + t] = s;
    }
}

// ---------------------------------------------------------------------------
// Kernel 2: per-query kNN (top-32 smallest dist^2 of 4096) + gather comb tile
//           + deterministic BN partial sums
// ---------------------------------------------------------------------------
__global__ void __launch_bounds__(256) k_knn(const float* __restrict__ keys,
                                             const float* __restrict__ points,
                                             const float* __restrict__ feats) {
    int bk  = blockIdx.x;
    int b   = bk >> 11;       // / 2048
    int k   = bk & 2047;
    int tid = threadIdx.x;

    __shared__ float d2[4096];
    __shared__ float wv[8];
    __shared__ int   wi[8];
    __shared__ int   sel[KNBR];
    __shared__ int   besti;

    float kx = keys[(b * KK + k) * 3 + 0];
    float ky = keys[(b * KK + k) * 3 + 1];
    float kz = keys[(b * KK + k) * 3 + 2];
    const float* pb = points + (size_t)b * NN * 3;

    #pragma unroll
    for (int t = 0; t < 16; t++) {
        int p = tid + t * 256;
        float dx = pb[p * 3 + 0] - kx;
        float dy = pb[p * 3 + 1] - ky;
        float dz = pb[p * 3 + 2] - kz;
        d2[p] = dx * dx + dy * dy + dz * dz;
    }
    __syncthreads();

    // per-thread local min over its 16 strided elements
    float lv = d2[tid]; int li = tid;
    #pragma unroll
    for (int t = 1; t < 16; t++) {
        int p = tid + t * 256;
        float v = d2[p];
        if (v < lv || (v == lv && p < li)) { lv = v; li = p; }
    }

    // 32 rounds of block-argmin; only the winner rescans its slice
    for (int r = 0; r < KNBR; r++) {
        float rv = lv; int ri = li;
        #pragma unroll
        for (int off = 16; off; off >>= 1) {
            float ov = __shfl_down_sync(0xffffffffu, rv, off);
            int   oi = __shfl_down_sync(0xffffffffu, ri, off);
            if (ov < rv || (ov == rv && oi < ri)) { rv = ov; ri = oi; }
        }
        if ((tid & 31) == 0) { wv[tid >> 5] = rv; wi[tid >> 5] = ri; }
        __syncthreads();
        if (tid == 0) {
            float bv = wv[0]; int bi = wi[0];
            #pragma unroll
            for (int w = 1; w < 8; w++)
                if (wv[w] < bv || (wv[w] == bv && wi[w] < bi)) { bv = wv[w]; bi = wi[w]; }
            sel[r] = bi;
            besti  = bi;
        }
        __syncthreads();
        int gb = besti;
        if ((gb & 255) == tid) {
            d2[gb] = INFINITY;
            lv = d2[tid]; li = tid;
            #pragma unroll
            for (int t = 1; t < 16; t++) {
                int p = tid + t * 256;
                float v = d2[p];
                if (v < lv || (v == lv && p < li)) { lv = v; li = p; }
            }
        }
        __syncthreads();
    }

    // gather comb = [rel(3) | feats(61)] for each selected neighbor into smem
    // (reuse d2 space) + write to global scratch (coalesced)
    float* cs = d2;
    const float* fb = feats + (size_t)b * NN * CIN;
    #pragma unroll
    for (int t = 0; t < 8; t++) {
        int e = tid + t * 256;           // e in [0, 2048)
        int n = e >> 6, c = e & 63;
        int p = sel[n];
        float v;
        if (c < 3) {
            float kc = (c == 0) ? kx : ((c == 1) ? ky : kz);
            v = pb[p * 3 + c] - kc;
        } else {
            v = fb[p * CIN + (c - 3)];
        }
        cs[e] = v;
        g_comb[(size_t)bk * 2048 + e] = v;
    }
    __syncthreads();

    if (tid < 64) {
        float s = 0.f, ss = 0.f;
        #pragma unroll
        for (int n = 0; n < KNBR; n++) {
            float v = cs[n * 64 + tid];
            s += v; ss += v * v;
        }
        g_part[(size_t)bk * 128 + tid]      = s;
        g_part[(size_t)bk * 128 + 64 + tid] = ss;
    }
}

// ---------------------------------------------------------------------------
// Kernel 3: finalize BN stats (double-precision reduce, deterministic)
// ---------------------------------------------------------------------------
__global__ void k_stats(const float* __restrict__ gamma) {
    int c = blockIdx.x;      // 64 channels
    int t = threadIdx.x;     // 128 threads
    double s = 0.0, ss = 0.0;
    for (int bk = t; bk < NBK; bk += 128) {
        s  += (double)g_part[(size_t)bk * 128 + c];
        ss += (double)g_part[(size_t)bk * 128 + 64 + c];
    }
    __shared__ double rs[128], rss[128];
    rs[t] = s; rss[t] = ss;
    __syncthreads();
    for (int o = 64; o; o >>= 1) {
        if (t < o) { rs[t] += rs[t + o]; rss[t] += rss[t + o]; }
        __syncthreads();
    }
    if (t == 0) {
        double mean = rs[0] / CNTF;
        double var  = rss[0] / CNTF - mean * mean;
        g_stats[c]      = (float)mean;
        g_stats[64 + c] = (float)(1.0 / sqrt(var + 1e-5)) * gamma[c];
    }
}

// ---------------------------------------------------------------------------
// Kernel 4: fused per-query pipeline. 128 threads per (b,k).
// smem pool (12288 floats = 48KB dynamic):
//   [0,2048)     comb  -> later lat
//   [2048,4096)  norm
//   [4096,8192)  h1    -> later s1 [4096,6144) and s2 [6144,8192)
//   [8192,12288) h2    -> later s3 [8192,10240)
// ---------------------------------------------------------------------------
__global__ void __launch_bounds__(128) k_main(
    const float* __restrict__ nxw1, const float* __restrict__ nxb1,
    const float* __restrict__ nxw2, const float* __restrict__ nxb2,
    const float* __restrict__ nxw3, const float* __restrict__ nxb3,
    const float* __restrict__ sxw1, const float* __restrict__ sxb1,
    const float* __restrict__ sxw2, const float* __restrict__ sxb2,
    const float* __restrict__ sxw3, const float* __restrict__ sxb3,
    const float* __restrict__ bnbeta,
    float* __restrict__ out)
{
    extern __shared__ float sm[];
    float* comb = sm;
    float* nrm  = sm + 2048;
    float* h1   = sm + 4096;
    float* h2   = sm + 8192;
    float* lat  = sm;           // reuses comb
    float* s1   = sm + 4096;    // reuses h1
    float* s2   = sm + 6144;
    float* s3   = sm + 8192;    // reuses h2
    __shared__ float setf[64];
    __shared__ float gh[4];
    __shared__ float ebuf[128];
    __shared__ float wbuf[128];

    int bk  = blockIdx.x;
    int tid = threadIdx.x;

    // Stage 1: load comb + compute norm
    #pragma unroll
    for (int t = 0; t < 16; t++) {
        int e = tid + t * 128;
        float v = g_comb[(size_t)bk * 2048 + e];
        int c = e & 63;
        comb[e] = v;
        nrm[e]  = (v - g_stats[c]) * g_stats[64 + c] + bnbeta[c];
    }
    __syncthreads();

    // Stage 2: h1 = relu(comb @ nxw1 + b1)    [32 x 128]
    {
        int j = tid;
        float acc[32];
        #pragma unroll
        for (int n = 0; n < 32; n++) acc[n] = 0.f;
        for (int c = 0; c < 64; c += 4) {
            float w0 = nxw1[(c + 0) * 128 + j];
            float w1 = nxw1[(c + 1) * 128 + j];
            float w2 = nxw1[(c + 2) * 128 + j];
            float w3 = nxw1[(c + 3) * 128 + j];
            #pragma unroll
            for (int n = 0; n < 32; n++) {
                float4 cb = *(const float4*)(comb + n * 64 + c);
                acc[n] += cb.x * w0 + cb.y * w1 + cb.z * w2 + cb.w * w3;
            }
        }
        float bj = nxb1[j];
        #pragma unroll
        for (int n = 0; n < 32; n++) h1[n * 128 + j] = fmaxf(acc[n] + bj, 0.f);
    }
    __syncthreads();

    // Stage 3: h2 = relu(h1 @ nxw2 + b2)      [32 x 128]
    {
        int j = tid;
        float acc[32];
        #pragma unroll
        for (int n = 0; n < 32; n++) acc[n] = 0.f;
        for (int c = 0; c < 128; c += 4) {
            float w0 = nxw2[(c + 0) * 128 + j];
            float w1 = nxw2[(c + 1) * 128 + j];
            float w2 = nxw2[(c + 2) * 128 + j];
            float w3 = nxw2[(c + 3) * 128 + j];
            #pragma unroll
            for (int n = 0; n < 32; n++) {
                float4 hb = *(const float4*)(h1 + n * 128 + c);
                acc[n] += hb.x * w0 + hb.y * w1 + hb.z * w2 + hb.w * w3;
            }
        }
        float bj = nxb2[j];
        #pragma unroll
        for (int n = 0; n < 32; n++) h2[n * 128 + j] = fmaxf(acc[n] + bj, 0.f);
    }
    __syncthreads();

    // Stage 4: lat = h2 @ nxw3 + b3           [32 x 64] (into comb region)
    {
        int o  = tid & 63;
        int n0 = (tid >> 6) * 16;
        float acc[16];
        #pragma unroll
        for (int n = 0; n < 16; n++) acc[n] = 0.f;
        for (int c = 0; c < 128; c += 4) {
            float w0 = nxw3[(c + 0) * 64 + o];
            float w1 = nxw3[(c + 1) * 64 + o];
            float w2 = nxw3[(c + 2) * 64 + o];
            float w3 = nxw3[(c + 3) * 64 + o];
            #pragma unroll
            for (int n = 0; n < 16; n++) {
                float4 hb = *(const float4*)(h2 + (n0 + n) * 128 + c);
                acc[n] += hb.x * w0 + hb.y * w1 + hb.z * w2 + hb.w * w3;
            }
        }
        float bo = nxb3[o];
        #pragma unroll
        for (int n = 0; n < 16; n++) lat[(n0 + n) * 64 + o] = acc[n] + bo;
    }
    __syncthreads();

    // Stage 5a: s1 = relu(nrm @ sxw1 + b)     [32 x 64]
    {
        int o  = tid & 63;
        int n0 = (tid >> 6) * 16;
        float acc[16];
        #pragma unroll
        for (int n = 0; n < 16; n++) acc[n] = 0.f;
        for (int c = 0; c < 64; c += 4) {
            float w0 = sxw1[(c + 0) * 64 + o];
            float w1 = sxw1[(c + 1) * 64 + o];
            float w2 = sxw1[(c + 2) * 64 + o];
            float w3 = sxw1[(c + 3) * 64 + o];
            #pragma unroll
            for (int n = 0; n < 16; n++) {
                float4 xb = *(const float4*)(nrm + (n0 + n) * 64 + c);
                acc[n] += xb.x * w0 + xb.y * w1 + xb.z * w2 + xb.w * w3;
            }
        }
        float bo = sxb1[o];
        #pragma unroll
        for (int n = 0; n < 16; n++) s1[(n0 + n) * 64 + o] = fmaxf(acc[n] + bo, 0.f);
    }
    __syncthreads();

    // Stage 5b: s2 = relu(s1 @ sxw2 + b)
    {
        int o  = tid & 63;
        int n0 = (tid >> 6) * 16;
        float acc[16];
        #pragma unroll
        for (int n = 0; n < 16; n++) acc[n] = 0.f;
        for (int c = 0; c < 64; c += 4) {
            float w0 = sxw2[(c + 0) * 64 + o];
            float w1 = sxw2[(c + 1) * 64 + o];
            float w2 = sxw2[(c + 2) * 64 + o];
            float w3 = sxw2[(c + 3) * 64 + o];
            #pragma unroll
            for (int n = 0; n < 16; n++) {
                float4 xb = *(const float4*)(s1 + (n0 + n) * 64 + c);
                acc[n] += xb.x * w0 + xb.y * w1 + xb.z * w2 + xb.w * w3;
            }
        }
        float bo = sxb2[o];
        #pragma unroll
        for (int n = 0; n < 16; n++) s2[(n0 + n) * 64 + o] = fmaxf(acc[n] + bo, 0.f);
    }
    __syncthreads();

    // Stage 5c: s3 = s2 @ sxw3 + b  (no relu)
    {
        int o  = tid & 63;
        int n0 = (tid >> 6) * 16;
        float acc[16];
        #pragma unroll
        for (int n = 0; n < 16; n++) acc[n] = 0.f;
        for (int c = 0; c < 64; c += 4) {
            float w0 = sxw3[(c + 0) * 64 + o];
            float w1 = sxw3[(c + 1) * 64 + o];
            float w2 = sxw3[(c + 2) * 64 + o];
            float w3 = sxw3[(c + 3) * 64 + o];
            #pragma unroll
            for (int n = 0; n < 16; n++) {
                float4 xb = *(const float4*)(s2 + (n0 + n) * 64 + c);
                acc[n] += xb.x * w0 + xb.y * w1 + xb.z * w2 + xb.w * w3;
            }
        }
        float bo = sxb3[o];
        #pragma unroll
        for (int n = 0; n < 16; n++) s3[(n0 + n) * 64 + o] = acc[n] + bo;
    }
    __syncthreads();

    // set_feat = sum over neighbors of s3
    if (tid < 64) {
        float s = 0.f;
        #pragma unroll
        for (int n = 0; n < 32; n++) s += s3[n * 64 + tid];
        setf[tid] = s;
    }
    __syncthreads();

    // gh[h] = c0[h] + sum_c setf[c] * A[64+c][h]
    if (tid < 4) {
        float s = g_A[512 + tid];
        #pragma unroll 8
        for (int c = 0; c < 64; c++) s += setf[c] * g_A[(64 + c) * 4 + tid];
        gh[tid] = s;
    }
    __syncthreads();

    // e[n][h] = gh[h] + sum_c nrm[n][c] * A[c][h]
    {
        int n = tid >> 2, h = tid & 3;
        float s = gh[h];
        #pragma unroll 8
        for (int c = 0; c < 64; c++) s += nrm[n * 64 + c] * g_A[c * 4 + h];
        ebuf[tid] = s;
    }
    __syncthreads();

    // softmax over neighbor axis (per head)
    if (tid < 4) {
        int h = tid;
        float m = -INFINITY;
        #pragma unroll
        for (int n = 0; n < 32; n++) m = fmaxf(m, ebuf[n * 4 + h]);
        float s = 0.f;
        #pragma unroll
        for (int n = 0; n < 32; n++) {
            float ex = expf(ebuf[n * 4 + h] - m);
            wbuf[n * 4 + h] = ex;
            s += ex;
        }
        float inv = 1.f / s;
        #pragma unroll
        for (int n = 0; n < 32; n++) wbuf[n * 4 + h] *= inv;
    }
    __syncthreads();

    // out[o][h] = sum_n lat[n][o] * w[n][h]  -> d_out[bk*256 + o*4 + h]
    #pragma unroll
    for (int r = 0; r < 2; r++) {
        int idx = tid + r * 128;
        int o = idx >> 2, h = idx & 3;
        float s = 0.f;
        #pragma unroll
        for (int n = 0; n < 32; n++) s += lat[n * 64 + o] * wbuf[n * 4 + h];
        out[(size_t)bk * 256 + idx] = s;
    }
}

// ---------------------------------------------------------------------------
extern "C" void kernel_launch(void* const* d_in, const int* in_sizes, int n_in,
                              void* d_out, int out_size) {
    (void)in_sizes; (void)n_in; (void)out_size;
    const float* keys  = (const float*)d_in[0];
    const float* points= (const float*)d_in[1];
    const float* feats = (const float*)d_in[2];
    const float* nxw1  = (const float*)d_in[3];
    const float* nxb1  = (const float*)d_in[4];
    const float* nxw2  = (const float*)d_in[5];
    const float* nxb2  = (const float*)d_in[6];
    const float* nxw3  = (const float*)d_in[7];
    const float* nxb3  = (const float*)d_in[8];
    const float* sxw1  = (const float*)d_in[9];
    const float* sxb1  = (const float*)d_in[10];
    const float* sxw2  = (const float*)d_in[11];
    const float* sxb2  = (const float*)d_in[12];
    const float* sxw3  = (const float*)d_in[13];
    const float* sxb3  = (const float*)d_in[14];
    const float* attw  = (const float*)d_in[15];
    const float* attb  = (const float*)d_in[16];
    const float* attq  = (const float*)d_in[17];
    const float* gamma = (const float*)d_in[18];
    const float* beta  = (const float*)d_in[19];
    float* out = (float*)d_out;

    cudaFuncSetAttribute(k_main, cudaFuncAttributeMaxDynamicSharedMemorySize, 49152);

    k_prep<<<2, 256>>>(attw, attb, attq);
    k_knn<<<NBK, 256>>>(keys, points, feats);
    k_stats<<<64, 128>>>(gamma);
    k_main<<<NBK, 128, 49152>>>(nxw1, nxb1, nxw2, nxb2, nxw3, nxb3,
                                sxw1, sxb1, sxw2, sxb2, sxw3, sxb3,
                                beta, out);
}

// round 3
// speedup vs baseline: 1.3928x; 1.3928x over previous
#include <cuda_runtime.h>
#include <math.h>
#include <stdint.h>

// Problem constants
#define BB 4
#define KK 2048
#define NN 4096
#define CIN 61
#define NBK (BB*KK)            // 8192 queries
#define NPTS (BB*NN)           // 16384 points
#define KNBR 32
#define CNTF 262144.0

typedef unsigned long long ull;

// Scratch (static device globals — allocation-free)
__device__ float g_part[(size_t)NBK * 128];     // BN partials
__device__ float g_A[516];                      // folded att: A[128][4] + c0[4]
__device__ int   g_selg[(size_t)NBK * KNBR];    // global point row per slot
__device__ float g_rel[(size_t)NBK * KNBR * 3]; // rel vectors per slot
__device__ float g_h1pre[(size_t)NPTS * 128];   // feats part of nx layer1
__device__ float g_s1pre[(size_t)NPTS * 64];    // feats part of sx layer1 (BN-folded)
__device__ float g_epre[(size_t)NPTS * 4];      // feats part of att matvec (BN-folded)
__device__ float g_sc[64], g_tc[64];            // BN affine: x*sc + tc
__device__ float g_C1[64], g_Ce[4];             // folded constants
__device__ float g_Wr1s[192], g_A1s[12];        // BN-scaled rel weights

// ---------------- packed f32x2 helpers ----------------
__device__ __forceinline__ ull ffma2(ull a, ull b, ull c) {
    ull d;
    asm("fma.rn.f32x2 %0, %1, %2, %3;" : "=l"(d) : "l"(a), "l"(b), "l"(c));
    return d;
}
__device__ __forceinline__ ull pk2(float lo, float hi) {
    ull d;
    asm("mov.b64 %0, {%1, %2};" : "=l"(d) : "f"(lo), "f"(hi));
    return d;
}
__device__ __forceinline__ float hsum2(ull a) {
    float lo, hi;
    asm("mov.b64 {%0, %1}, %2;" : "=f"(lo), "=f"(hi) : "l"(a));
    return lo + hi;
}

// ---------------------------------------------------------------------------
// Kernel 1: fold attention weights: A[c][h] = sum_o att_w[c, h*64+o]*att_q[h,o]
// ---------------------------------------------------------------------------
__global__ void k_prep(const float* __restrict__ att_w,
                       const float* __restrict__ att_b,
                       const float* __restrict__ att_q) {
    int t = blockIdx.x * blockDim.x + threadIdx.x;
    if (t < 512) {
        int c = t >> 2, h = t & 3;
        float s = 0.f;
        #pragma unroll 8
        for (int o = 0; o < 64; o++)
            s += att_w[c * 256 + h * 64 + o] * att_q[h * 64 + o];
        g_A[t] = s;
    }
    if (t < 4) {
        float s = 0.f;
        #pragma unroll 8
        for (int o = 0; o < 64; o++)
            s += att_b[t * 64 + o] * att_q[t * 64 + o];
        g_A[512 + t] = s;
    }
}

// ---------------------------------------------------------------------------
// Kernel 1b: per-point feats part of nx layer1: h1pre[row][j]
// ---------------------------------------------------------------------------
__global__ void __launch_bounds__(128) k_pre_h1(const float* __restrict__ feats,
                                                const float* __restrict__ nxw1) {
    int row = blockIdx.x;                 // 0..16383
    int t = threadIdx.x;                  // 128
    __shared__ float f[61];
    if (t < 61) f[t] = feats[(size_t)row * 61 + t];
    __syncthreads();
    float acc = 0.f;
    #pragma unroll 
    for (int c = 0; c < 61; c++) acc += f[c] * nxw1[(3 + c) * 128 + t];
    g_h1pre[(size_t)row * 128 + t] = acc;
}

// ---------------------------------------------------------------------------
// Kernel 2: per-query kNN + BN partials + store sel/rel
// ---------------------------------------------------------------------------
__global__ void __launch_bounds__(256) k_knn(const float* __restrict__ keys,
                                             const float* __restrict__ points,
                                             const float* __restrict__ feats) {
    int bk  = blockIdx.x;
    int b   = bk >> 11;
    int k   = bk & 2047;
    int tid = threadIdx.x;

    __shared__ float d2[4096];
    __shared__ float wv[8];
    __shared__ int   wi[8];
    __shared__ int   sel[KNBR];
    __shared__ int   besti;

    float kx = keys[(b * KK + k) * 3 + 0];
    float ky = keys[(b * KK + k) * 3 + 1];
    float kz = keys[(b * KK + k) * 3 + 2];
    const float* pb = points + (size_t)b * NN * 3;

    #pragma unroll
    for (int t = 0; t < 16; t++) {
        int p = tid + t * 256;
        float dx = pb[p * 3 + 0] - kx;
        float dy = pb[p * 3 + 1] - ky;
        float dz = pb[p * 3 + 2] - kz;
        d2[p] = dx * dx + dy * dy + dz * dz;
    }
    __syncthreads();

    float lv = d2[tid]; int li = tid;
    #pragma unroll
    for (int t = 1; t < 16; t++) {
        int p = tid + t * 256;
        float v = d2[p];
        if (v < lv || (v == lv && p < li)) { lv = v; li = p; }
    }

    for (int r = 0; r < KNBR; r++) {
        float rv = lv; int ri = li;
        #pragma unroll
        for (int off = 16; off; off >>= 1) {
            float ov = __shfl_down_sync(0xffffffffu, rv, off);
            int   oi = __shfl_down_sync(0xffffffffu, ri, off);
            if (ov < rv || (ov == rv && oi < ri)) { rv = ov; ri = oi; }
        }
        if ((tid & 31) == 0) { wv[tid >> 5] = rv; wi[tid >> 5] = ri; }
        __syncthreads();
        if (tid == 0) {
            float bv = wv[0]; int bi = wi[0];
            #pragma unroll
            for (int w = 1; w < 8; w++)
                if (wv[w] < bv || (wv[w] == bv && wi[w] < bi)) { bv = wv[w]; bi = wi[w]; }
            sel[r] = bi;
            besti  = bi;
        }
        __syncthreads();
        int gb = besti;
        if ((gb & 255) == tid) {
            d2[gb] = INFINITY;
            lv = d2[tid]; li = tid;
            #pragma unroll
            for (int t = 1; t < 16; t++) {
                int p = tid + t * 256;
                float v = d2[p];
                if (v < lv || (v == lv && p < li)) { lv = v; li = p; }
            }
        }
        __syncthreads();
    }

    // gather comb into smem (reuse d2) for BN partials + rel extraction
    float* cs = d2;
    const float* fb = feats + (size_t)b * NN * CIN;
    #pragma unroll
    for (int t = 0; t < 8; t++) {
        int e = tid + t * 256;
        int n = e >> 6, c = e & 63;
        int p = sel[n];
        float v;
        if (c < 3) {
            float kc = (c == 0) ? kx : ((c == 1) ? ky : kz);
            v = pb[p * 3 + c] - kc;
        } else {
            v = fb[p * CIN + (c - 3)];
        }
        cs[e] = v;
    }
    __syncthreads();

    if (tid < 64) {
        float s = 0.f, ss = 0.f;
        #pragma unroll
        for (int n = 0; n < KNBR; n++) {
            float v = cs[n * 64 + tid];
            s += v; ss += v * v;
        }
        g_part[(size_t)bk * 128 + tid]      = s;
        g_part[(size_t)bk * 128 + 64 + tid] = ss;
    }
    if (tid < 32) g_selg[(size_t)bk * 32 + tid] = b * NN + sel[tid];
    if (tid < 96) {
        int n = tid / 3, c = tid % 3;
        g_rel[(size_t)bk * 96 + tid] = cs[n * 64 + c];
    }
}

// ---------------------------------------------------------------------------
// Kernel 3: finalize BN stats -> per-channel affine sc/tc
// ---------------------------------------------------------------------------
__global__ void k_stats(const float* __restrict__ gamma,
                        const float* __restrict__ beta) {
    int c = blockIdx.x;
    int t = threadIdx.x;
    double s = 0.0, ss = 0.0;
    for (int bk = t; bk < NBK; bk += 128) {
        s  += (double)g_part[(size_t)bk * 128 + c];
        ss += (double)g_part[(size_t)bk * 128 + 64 + c];
    }
    __shared__ double rs[128], rss[128];
    rs[t] = s; rss[t] = ss;
    __syncthreads();
    for (int o = 64; o; o >>= 1) {
        if (t < o) { rs[t] += rs[t + o]; rss[t] += rss[t + o]; }
        __syncthreads();
    }
    if (t == 0) {
        double mean = rs[0] / CNTF;
        double var  = rss[0] / CNTF - mean * mean;
        float sc = (float)((1.0 / sqrt(var + 1e-5)) * (double)gamma[c]);
        g_sc[c] = sc;
        g_tc[c] = beta[c] - (float)mean * sc;
    }
}

// ---------------------------------------------------------------------------
// Kernel 3b: fold constants that depend on BN stats
// ---------------------------------------------------------------------------
__global__ void k_const(const float* __restrict__ sxw1,
                        const float* __restrict__ sxb1) {
    int t = threadIdx.x;   // 256
    if (t < 64) {
        float s = sxb1[t];
        #pragma unroll 8
        for (int c = 0; c < 64; c++) s += g_tc[c] * sxw1[c * 64 + t];
        g_C1[t] = s;
    }
    if (t < 4) {
        float s = g_A[512 + t];
        #pragma unroll 8
        for (int c = 0; c < 64; c++) s += g_tc[c] * g_A[c * 4 + t];
        g_Ce[t] = s;
    }
    if (t >= 64) {
        int i = t - 64;              // 0..191
        int c = i >> 6, o = i & 63;
        g_Wr1s[i] = g_sc[c] * sxw1[c * 64 + o];
    }
    if (t < 12) {
        int c = t >> 2, h = t & 3;
        g_A1s[t] = g_sc[c] * g_A[c * 4 + h];
    }
}

// ---------------------------------------------------------------------------
// Kernel 3c: per-point feats part of sx layer1 + att matvec (BN-folded)
// ---------------------------------------------------------------------------
__global__ void __launch_bounds__(64) k_pre_s1e(const float* __restrict__ feats,
                                                const float* __restrict__ sxw1) {
    int row = blockIdx.x;
    int t = threadIdx.x;   // 64
    __shared__ float sf[61];
    if (t < 61) sf[t] = feats[(size_t)row * 61 + t] * g_sc[3 + t];
    __syncthreads();
    float acc = 0.f;
    #pragma unroll 
    for (int c = 0; c < 61; c++) acc += sf[c] * sxw1[(3 + c) * 64 + t];
    g_s1pre[(size_t)row * 64 + t] = acc;
    if (t < 4) {
        float s = 0.f;
        #pragma unroll 
        for (int c = 0; c < 61; c++) s += sf[c] * g_A[(3 + c) * 4 + t];
        g_epre[(size_t)row * 4 + t] = s;
    }
}

// ---------------------------------------------------------------------------
// Kernel 4: fused per-query pipeline. 256 threads per (b,k). 32KB dyn smem.
//   buf: [0,4096) h1 -> lat[0,2048) + s1[2048,4096)
//        [4096,8192) h2 -> s2[4096,6144) + s3[6144,8192)
// ---------------------------------------------------------------------------
__global__ void __launch_bounds__(256, 4) k_main(
    const float* __restrict__ nxw1, const float* __restrict__ nxb1,
    const float* __restrict__ nxw2, const float* __restrict__ nxb2,
    const float* __restrict__ nxw3, const float* __restrict__ nxb3,
    const float* __restrict__ sxw2, const float* __restrict__ sxb2,
    const float* __restrict__ sxw3, const float* __restrict__ sxb3,
    float* __restrict__ out)
{
    extern __shared__ float sm[];
    float* h1  = sm;            // [32][128]
    float* h2  = sm + 4096;     // [32][128]
    float* lat = sm;            // [32][64]
    float* s1  = sm + 2048;     // [32][64]
    float* s2  = sm + 4096;     // [32][64]
    float* s3  = sm + 6144;     // [32][64]
    __shared__ float rel_s[96];
    __shared__ int   sel_s[32];
    __shared__ float setf[64];
    __shared__ float gh[4];
    __shared__ float ebuf[128];
    __shared__ float wbuf[128];

    int bk = blockIdx.x;
    int t  = threadIdx.x;

    if (t < 32) sel_s[t] = g_selg[(size_t)bk * 32 + t];
    if (t >= 32 && t < 128) rel_s[t - 32 + 0] = g_rel[(size_t)bk * 96 + (t - 32)];
    __syncthreads();

    // Stage A: h1[n][j] = relu(h1pre[pt][j] + rel . w1[0:3][j] + b1[j])
    {
        int j  = t & 127;
        int nb = (t >> 7) * 16;
        float wr0 = nxw1[j], wr1 = nxw1[128 + j], wr2 = nxw1[256 + j], bj = nxb1[j];
        #pragma unroll
        for (int i = 0; i < 16; i++) {
            int n = nb + i;
            float acc = g_h1pre[(size_t)sel_s[n] * 128 + j] + bj
                      + rel_s[n * 3] * wr0 + rel_s[n * 3 + 1] * wr1 + rel_s[n * 3 + 2] * wr2;
            h1[n * 128 + j] = fmaxf(acc, 0.f);
        }
    }
    __syncthreads();

    // Stage B: h2 = relu(h1 @ nxw2 + b2)  [32 x 128], packed f32x2
    {
        int j0 = t & 63;
        int j1 = j0 + 64;
        int nb = (t >> 6) * 8;
        ull a0[8], a1[8];
        #pragma unroll
        for (int i = 0; i < 8; i++) { a0[i] = 0ull; a1[i] = 0ull; }
        for (int c = 0; c < 128; c += 4) {
            float wA0 = nxw2[c * 128 + j0],       wA1 = nxw2[(c + 1) * 128 + j0];
            float wA2 = nxw2[(c + 2) * 128 + j0], wA3 = nxw2[(c + 3) * 128 + j0];
            float wB0 = nxw2[c * 128 + j1],       wB1 = nxw2[(c + 1) * 128 + j1];
            float wB2 = nxw2[(c + 2) * 128 + j1], wB3 = nxw2[(c + 3) * 128 + j1];
            ull wa01 = pk2(wA0, wA1), wa23 = pk2(wA2, wA3);
            ull wb01 = pk2(wB0, wB1), wb23 = pk2(wB2, wB3);
            #pragma unroll
            for (int i = 0; i < 8; i++) {
                ulonglong2 x = *(const ulonglong2*)(h1 + (nb + i) * 128 + c);
                a0[i] = ffma2(x.x, wa01, a0[i]);
                a0[i] = ffma2(x.y, wa23, a0[i]);
                a1[i] = ffma2(x.x, wb01, a1[i]);
                a1[i] = ffma2(x.y, wb23, a1[i]);
            }
        }
        float b0 = nxb2[j0], b1v = nxb2[j1];
        #pragma unroll
        for (int i = 0; i < 8; i++) {
            h2[(nb + i) * 128 + j0] = fmaxf(hsum2(a0[i]) + b0, 0.f);
            h2[(nb + i) * 128 + j1] = fmaxf(hsum2(a1[i]) + b1v, 0.f);
        }
    }
    __syncthreads();

    // Stage C: lat = h2 @ nxw3 + b3  [32 x 64]
    {
        int o0 = t & 31;
        int o1 = o0 + 32;
        int nb = (t >> 5) * 4;
        ull a0[4], a1[4];
        #pragma unroll
        for (int i = 0; i < 4; i++) { a0[i] = 0ull; a1[i] = 0ull; }
        for (int c = 0; c < 128; c += 4) {
            float wA0 = nxw3[c * 64 + o0],       wA1 = nxw3[(c + 1) * 64 + o0];
            float wA2 = nxw3[(c + 2) * 64 + o0], wA3 = nxw3[(c + 3) * 64 + o0];
            float wB0 = nxw3[c * 64 + o1],       wB1 = nxw3[(c + 1) * 64 + o1];
            float wB2 = nxw3[(c + 2) * 64 + o1], wB3 = nxw3[(c + 3) * 64 + o1];
            ull wa01 = pk2(wA0, wA1), wa23 = pk2(wA2, wA3);
            ull wb01 = pk2(wB0, wB1), wb23 = pk2(wB2, wB3);
            #pragma unroll
            for (int i = 0; i < 4; i++) {
                ulonglong2 x = *(const ulonglong2*)(h2 + (nb + i) * 128 + c);
                a0[i] = ffma2(x.x, wa01, a0[i]);
                a0[i] = ffma2(x.y, wa23, a0[i]);
                a1[i] = ffma2(x.x, wb01, a1[i]);
                a1[i] = ffma2(x.y, wb23, a1[i]);
            }
        }
        float b0 = nxb3[o0], b1v = nxb3[o1];
        #pragma unroll
        for (int i = 0; i < 4; i++) {
            lat[(nb + i) * 64 + o0] = hsum2(a0[i]) + b0;
            lat[(nb + i) * 64 + o1] = hsum2(a1[i]) + b1v;
        }
    }
    __syncthreads();

    // Stage D: s1[n][o] = relu(s1pre[pt][o] + rel . Wr1s + C1[o])
    {
        int o  = t & 63;
        int nb = (t >> 6) * 8;
        float w0 = g_Wr1s[o], w1 = g_Wr1s[64 + o], w2 = g_Wr1s[128 + o], c1 = g_C1[o];
        #pragma unroll
        for (int i = 0; i < 8; i++) {
            int n = nb + i;
            float acc = g_s1pre[(size_t)sel_s[n] * 64 + o] + c1
                      + rel_s[n * 3] * w0 + rel_s[n * 3 + 1] * w1 + rel_s[n * 3 + 2] * w2;
            s1[n * 64 + o] = fmaxf(acc, 0.f);
        }
    }
    __syncthreads();

    // Stage E: s2 = relu(s1 @ sxw2 + b)  [32 x 64]
    {
        int o0 = t & 31;
        int o1 = o0 + 32;
        int nb = (t >> 5) * 4;
        ull a0[4], a1[4];
        #pragma unroll
        for (int i = 0; i < 4; i++) { a0[i] = 0ull; a1[i] = 0ull; }
        for (int c = 0; c < 64; c += 4) {
            float wA0 = sxw2[c * 64 + o0],       wA1 = sxw2[(c + 1) * 64 + o0];
            float wA2 = sxw2[(c + 2) * 64 + o0], wA3 = sxw2[(c + 3) * 64 + o0];
            float wB0 = sxw2[c * 64 + o1],       wB1 = sxw2[(c + 1) * 64 + o1];
            float wB2 = sxw2[(c + 2) * 64 + o1], wB3 = sxw2[(c + 3) * 64 + o1];
            ull wa01 = pk2(wA0, wA1), wa23 = pk2(wA2, wA3);
            ull wb01 = pk2(wB0, wB1), wb23 = pk2(wB2, wB3);
            #pragma unroll
            for (int i = 0; i < 4; i++) {
                ulonglong2 x = *(const ulonglong2*)(s1 + (nb + i) * 64 + c);
                a0[i] = ffma2(x.x, wa01, a0[i]);
                a0[i] = ffma2(x.y, wa23, a0[i]);
                a1[i] = ffma2(x.x, wb01, a1[i]);
                a1[i] = ffma2(x.y, wb23, a1[i]);
            }
        }
        float b0 = sxb2[o0], b1v = sxb2[o1];
        #pragma unroll
        for (int i = 0; i < 4; i++) {
            s2[(nb + i) * 64 + o0] = fmaxf(hsum2(a0[i]) + b0, 0.f);
            s2[(nb + i) * 64 + o1] = fmaxf(hsum2(a1[i]) + b1v, 0.f);
        }
    }
    __syncthreads();

    // Stage F: s3 = s2 @ sxw3 + b  (no relu)
    {
        int o0 = t & 31;
        int o1 = o0 + 32;
        int nb = (t >> 5) * 4;
        ull a0[4], a1[4];
        #pragma unroll
        for (int i = 0; i < 4; i++) { a0[i] = 0ull; a1[i] = 0ull; }
        for (int c = 0; c < 64; c += 4) {
            float wA0 = sxw3[c * 64 + o0],       wA1 = sxw3[(c + 1) * 64 + o0];
            float wA2 = sxw3[(c + 2) * 64 + o0], wA3 = sxw3[(c + 3) * 64 + o0];
            float wB0 = sxw3[c * 64 + o1],       wB1 = sxw3[(c + 1) * 64 + o1];
            float wB2 = sxw3[(c + 2) * 64 + o1], wB3 = sxw3[(c + 3) * 64 + o1];
            ull wa01 = pk2(wA0, wA1), wa23 = pk2(wA2, wA3);
            ull wb01 = pk2(wB0, wB1), wb23 = pk2(wB2, wB3);
            #pragma unroll
            for (int i = 0; i < 4; i++) {
                ulonglong2 x = *(const ulonglong2*)(s2 + (nb + i) * 64 + c);
                a0[i] = ffma2(x.x, wa01, a0[i]);
                a0[i] = ffma2(x.y, wa23, a0[i]);
                a1[i] = ffma2(x.x, wb01, a1[i]);
                a1[i] = ffma2(x.y, wb23, a1[i]);
            }
        }
        float b0 = sxb3[o0], b1v = sxb3[o1];
        #pragma unroll
        for (int i = 0; i < 4; i++) {
            s3[(nb + i) * 64 + o0] = hsum2(a0[i]) + b0;
            s3[(nb + i) * 64 + o1] = hsum2(a1[i]) + b1v;
        }
    }
    __syncthreads();

    // set_feat + folded head bias
    if (t < 64) {
        float s = 0.f;
        #pragma unroll
        for (int n = 0; n < 32; n++) s += s3[n * 64 + t];
        setf[t] = s;
    }
    __syncthreads();
    if (t < 4) {
        float s = g_Ce[t];
        #pragma unroll 8
        for (int c = 0; c < 64; c++) s += setf[c] * g_A[(64 + c) * 4 + t];
        gh[t] = s;
    }
    __syncthreads();

    // e[n][h] = gh[h] + epre[pt][h] + rel . A1s
    if (t < 128) {
        int n = t >> 2, h = t & 3;
        float e = gh[h] + g_epre[(size_t)sel_s[n] * 4 + h]
                + rel_s[n * 3] * g_A1s[h]
                + rel_s[n * 3 + 1] * g_A1s[4 + h]
                + rel_s[n * 3 + 2] * g_A1s[8 + h];
        ebuf[t] = e;
    }
    __syncthreads();

    // softmax over neighbor axis (per head)
    if (t < 4) {
        int h = t;
        float m = -INFINITY;
        #pragma unroll
        for (int n = 0; n < 32; n++) m = fmaxf(m, ebuf[n * 4 + h]);
        float s = 0.f;
        #pragma unroll
        for (int n = 0; n < 32; n++) {
            float ex = expf(ebuf[n * 4 + h] - m);
            wbuf[n * 4 + h] = ex;
            s += ex;
        }
        float inv = 1.f / s;
        #pragma unroll
        for (int n = 0; n < 32; n++) wbuf[n * 4 + h] *= inv;
    }
    __syncthreads();

    // out[o][h] = sum_n lat[n][o] * w[n][h]
    {
        int o = t >> 2, h = t & 3;
        float s = 0.f;
        #pragma unroll
        for (int n = 0; n < 32; n++) s += lat[n * 64 + o] * wbuf[n * 4 + h];
        out[(size_t)bk * 256 + t] = s;
    }
}

// ---------------------------------------------------------------------------
extern "C" void kernel_launch(void* const* d_in, const int* in_sizes, int n_in,
                              void* d_out, int out_size) {
    (void)in_sizes; (void)n_in; (void)out_size;
    const float* keys  = (const float*)d_in[0];
    const float* points= (const float*)d_in[1];
    const float* feats = (const float*)d_in[2];
    const float* nxw1  = (const float*)d_in[3];
    const float* nxb1  = (const float*)d_in[4];
    const float* nxw2  = (const float*)d_in[5];
    const float* nxb2  = (const float*)d_in[6];
    const float* nxw3  = (const float*)d_in[7];
    const float* nxb3  = (const float*)d_in[8];
    const float* sxw1  = (const float*)d_in[9];
    const float* sxb1  = (const float*)d_in[10];
    const float* sxw2  = (const float*)d_in[11];
    const float* sxb2  = (const float*)d_in[12];
    const float* sxw3  = (const float*)d_in[13];
    const float* sxb3  = (const float*)d_in[14];
    const float* attw  = (const float*)d_in[15];
    const float* attb  = (const float*)d_in[16];
    const float* attq  = (const float*)d_in[17];
    const float* gamma = (const float*)d_in[18];
    const float* beta  = (const float*)d_in[19];
    float* out = (float*)d_out;

    k_prep<<<2, 256>>>(attw, attb, attq);
    k_pre_h1<<<NPTS, 128>>>(feats, nxw1);
    k_knn<<<NBK, 256>>>(keys, points, feats);
    k_stats<<<64, 128>>>(gamma, beta);
    k_const<<<1, 256>>>(sxw1, sxb1);
    k_pre_s1e<<<NPTS, 64>>>(feats, sxw1);
    k_main<<<NBK, 256, 32768>>>(nxw1, nxb1, nxw2, nxb2, nxw3, nxb3,
                                sxw2, sxb2, sxw3, sxb3, out);
}